// round 1
// baseline (speedup 1.0000x reference)
#include <cuda_runtime.h>
#include <math.h>

// ---------------------------------------------------------------------------
// DeepseekV2 MoE, fp32 end-to-end.
// Pipeline (single stream, 7 launches):
//   1. router_kernel     : logits -> sigmoid -> grouped topk -> (w, eidx)
//   2. dispatch_kernel   : ordered per-expert assignment lists (capacity drop)
//   3. shared_gateup     : x @ ws_gate_up  -> silu*mul -> act_s   [1024,1024]
//   4. shared_down       : act_s @ ws_down -> out (initializes d_out)
//   5. routed_gateup     : gather rows, per-expert GEMM + silu*mul -> act_r
//   6. routed_down       : per-expert GEMM -> ybuf[a, H]
//   7. combine           : out[t] += SCALE * sum_k w[t,k]*ybuf[t*K+k]
// ---------------------------------------------------------------------------

#define T_TOK   1024
#define H_DIM   1024
#define E_EXP   64
#define I_DIM   512
#define TOPK    6
#define NGROUP  8
#define TKG     3
#define CAP     256
#define A_TOT   (T_TOK * TOPK)          // 6144
#define SCALE_F 2.5f
#define GUP_COLS (2 * I_DIM)            // 1024 per expert (gate|up)
#define SH_ACT   1024                   // I * N_SHARED
#define SH_GUP   2048                   // 2 * I * N_SHARED

// ------------------------------- scratch -----------------------------------
__device__ float g_w[A_TOT];            // normalized routing weights
__device__ int   g_eidx[A_TOT];         // expert id per assignment
__device__ int   g_counts[E_EXP];
__device__ int   g_list[E_EXP * CAP];   // assignment id per (expert, slot)
__device__ int   g_keep[A_TOT];
__device__ float g_act_s[T_TOK * SH_ACT];          // 4 MB
__device__ float g_act_r[E_EXP * CAP * I_DIM];     // 32 MB
__device__ float g_ybuf[A_TOT * H_DIM];            // 24 MB

// ------------------------------- router ------------------------------------
__global__ __launch_bounds__(256) void router_kernel(
    const float* __restrict__ x, const float* __restrict__ gw,
    const float* __restrict__ bias)
{
    __shared__ float xs[H_DIM];
    __shared__ float lg[E_EXP];
    const int t = blockIdx.x, tid = threadIdx.x;

    *(float4*)&xs[tid * 4] = *(const float4*)(x + (size_t)t * H_DIM + tid * 4);
    __syncthreads();

    if (tid < E_EXP) {
        float acc = 0.f;
#pragma unroll 8
        for (int h = 0; h < H_DIM; h++)
            acc += xs[h] * gw[h * E_EXP + tid];
        lg[tid] = acc;
    }
    __syncthreads();

    if (tid == 0) {
        float sc[E_EXP], s[E_EXP];
#pragma unroll
        for (int e = 0; e < E_EXP; e++) {
            sc[e] = 1.f / (1.f + expf(-lg[e]));
            s[e]  = sc[e] + bias[e];
        }
        // per-group sum of top-2
        float gs[NGROUP];
#pragma unroll
        for (int g = 0; g < NGROUP; g++) {
            float m1 = -INFINITY, m2 = -INFINITY;
            for (int j = 0; j < E_EXP / NGROUP; j++) {
                float v = s[g * (E_EXP / NGROUP) + j];
                if (v > m1) { m2 = m1; m1 = v; }
                else if (v > m2) { m2 = v; }
            }
            gs[g] = m1 + m2;
        }
        bool gsel[NGROUP];
#pragma unroll
        for (int g = 0; g < NGROUP; g++) gsel[g] = false;
        for (int it = 0; it < TKG; it++) {
            int bi = -1; float bv = -INFINITY;
            for (int g = 0; g < NGROUP; g++)
                if (!gsel[g] && gs[g] > bv) { bv = gs[g]; bi = g; }
            gsel[bi] = true;
        }
        // top-K experts among selected groups (strict > : stable ties)
        bool used[E_EXP];
#pragma unroll
        for (int e = 0; e < E_EXP; e++) used[e] = false;
        int   idx[TOPK];
        float wv[TOPK];
        float wsum = 0.f;
        for (int k = 0; k < TOPK; k++) {
            int bi = -1; float bv = -INFINITY;
            for (int e = 0; e < E_EXP; e++) {
                if (!gsel[e / (E_EXP / NGROUP)] || used[e]) continue;
                if (s[e] > bv) { bv = s[e]; bi = e; }
            }
            used[bi] = true;
            idx[k] = bi;
            wv[k]  = sc[bi];
            wsum  += sc[bi];
        }
        float inv = 1.f / wsum;
        for (int k = 0; k < TOPK; k++) {
            g_w[t * TOPK + k]    = wv[k] * inv;
            g_eidx[t * TOPK + k] = idx[k];
        }
    }
}

// ------------------------------ dispatch -----------------------------------
// Ordered (by assignment index) slot assignment per expert -> matches the
// reference cumsum-based capacity drop exactly.
__global__ __launch_bounds__(256) void dispatch_kernel()
{
    const int e = blockIdx.x, tid = threadIdx.x;
    const int lane = tid & 31, wid = tid >> 5;
    __shared__ int warp_tot[8];
    int base = 0;
    for (int chunk = 0; chunk < A_TOT; chunk += 256) {
        int a = chunk + tid;
        int m = (a < A_TOT && g_eidx[a] == e) ? 1 : 0;
        unsigned bal = __ballot_sync(0xffffffffu, m);
        if (lane == 0) warp_tot[wid] = __popc(bal);
        __syncthreads();
        int woff = 0, tot = 0;
#pragma unroll
        for (int i = 0; i < 8; i++) { if (i < wid) woff += warp_tot[i]; tot += warp_tot[i]; }
        if (m) {
            int pos = base + woff + __popc(bal & ((1u << lane) - 1u));
            if (pos < CAP) g_list[e * CAP + pos] = a;
            g_keep[a] = (pos < CAP) ? 1 : 0;
        }
        base += tot;
        __syncthreads();
    }
    if (tid == 0) g_counts[e] = base < CAP ? base : CAP;
}

// --------------------- fused gate_up GEMM (shared experts) -----------------
// 64x64x16 tile, 4x4 micro-tile, dual accumulators (gate & up), silu*mul epi.
__global__ __launch_bounds__(256) void shared_gateup(
    const float* __restrict__ x, const float* __restrict__ W /*[H, 2048]*/)
{
    const int BK = 16;
    __shared__ float Xs[BK][68];
    __shared__ float Wg[BK][64];
    __shared__ float Wu[BK][64];
    const int tid = threadIdx.x;
    const int tx = tid & 15, ty = tid >> 4;
    const int rb = blockIdx.y * 64, cb = blockIdx.x * 64;

    float accG[4][4] = {}, accU[4][4] = {};

    const int lrow = tid >> 2, lk4 = (tid & 3) * 4;     // X loader
    const int wkk = tid >> 4, wcc = (tid & 15) * 4;     // W loader
    const float* xrow = x + (size_t)(rb + lrow) * H_DIM;

    for (int k0 = 0; k0 < H_DIM; k0 += BK) {
        float4 xa = *(const float4*)(xrow + k0 + lk4);
        Xs[lk4 + 0][lrow] = xa.x; Xs[lk4 + 1][lrow] = xa.y;
        Xs[lk4 + 2][lrow] = xa.z; Xs[lk4 + 3][lrow] = xa.w;
        *(float4*)&Wg[wkk][wcc] = *(const float4*)(W + (size_t)(k0 + wkk) * SH_GUP + cb + wcc);
        *(float4*)&Wu[wkk][wcc] = *(const float4*)(W + (size_t)(k0 + wkk) * SH_GUP + SH_ACT + cb + wcc);
        __syncthreads();
#pragma unroll
        for (int kk = 0; kk < BK; kk++) {
            float a[4], bg[4], bu[4];
#pragma unroll
            for (int i = 0; i < 4; i++) a[i] = Xs[kk][ty * 4 + i];
#pragma unroll
            for (int j = 0; j < 4; j++) { bg[j] = Wg[kk][tx * 4 + j]; bu[j] = Wu[kk][tx * 4 + j]; }
#pragma unroll
            for (int i = 0; i < 4; i++)
#pragma unroll
                for (int j = 0; j < 4; j++) {
                    accG[i][j] += a[i] * bg[j];
                    accU[i][j] += a[i] * bu[j];
                }
        }
        __syncthreads();
    }
#pragma unroll
    for (int i = 0; i < 4; i++) {
        int r = rb + ty * 4 + i;
#pragma unroll
        for (int j = 0; j < 4; j++) {
            int c = cb + tx * 4 + j;
            float g = accG[i][j], u = accU[i][j];
            g_act_s[(size_t)r * SH_ACT + c] = (g / (1.f + expf(-g))) * u;
        }
    }
}

// ----------------------- shared down GEMM (writes out) ---------------------
__global__ __launch_bounds__(256) void shared_down(
    const float* __restrict__ W /*[1024,1024]*/, float* __restrict__ out)
{
    const int BK = 16;
    __shared__ float Xs[BK][68];
    __shared__ float Ws[BK][64];
    const int tid = threadIdx.x;
    const int tx = tid & 15, ty = tid >> 4;
    const int rb = blockIdx.y * 64, cb = blockIdx.x * 64;
    float acc[4][4] = {};
    const int lrow = tid >> 2, lk4 = (tid & 3) * 4;
    const int wkk = tid >> 4, wcc = (tid & 15) * 4;
    const float* xrow = g_act_s + (size_t)(rb + lrow) * SH_ACT;

    for (int k0 = 0; k0 < SH_ACT; k0 += BK) {
        float4 xa = *(const float4*)(xrow + k0 + lk4);
        Xs[lk4 + 0][lrow] = xa.x; Xs[lk4 + 1][lrow] = xa.y;
        Xs[lk4 + 2][lrow] = xa.z; Xs[lk4 + 3][lrow] = xa.w;
        *(float4*)&Ws[wkk][wcc] = *(const float4*)(W + (size_t)(k0 + wkk) * H_DIM + cb + wcc);
        __syncthreads();
#pragma unroll
        for (int kk = 0; kk < BK; kk++) {
            float a[4], b[4];
#pragma unroll
            for (int i = 0; i < 4; i++) a[i] = Xs[kk][ty * 4 + i];
#pragma unroll
            for (int j = 0; j < 4; j++) b[j] = Ws[kk][tx * 4 + j];
#pragma unroll
            for (int i = 0; i < 4; i++)
#pragma unroll
                for (int j = 0; j < 4; j++) acc[i][j] += a[i] * b[j];
        }
        __syncthreads();
    }
#pragma unroll
    for (int i = 0; i < 4; i++) {
        int r = rb + ty * 4 + i;
#pragma unroll
        for (int j = 0; j < 4; j++)
            out[(size_t)r * H_DIM + cb + tx * 4 + j] = acc[i][j];
    }
}

// -------------------- routed gate_up (gathered rows) -----------------------
__global__ __launch_bounds__(256) void routed_gateup(
    const float* __restrict__ x, const float* __restrict__ Wall /*[E,H,1024]*/)
{
    const int BK = 16;
    const int e = blockIdx.z;
    const int cnt = g_counts[e];
    const int r0 = blockIdx.y * 64;
    if (r0 >= cnt) return;

    __shared__ float Xs[BK][68];
    __shared__ float Wg[BK][64];
    __shared__ float Wu[BK][64];
    const int tid = threadIdx.x;
    const int tx = tid & 15, ty = tid >> 4;
    const int cb = blockIdx.x * 64;
    const float* W = Wall + (size_t)e * H_DIM * GUP_COLS;

    float accG[4][4] = {}, accU[4][4] = {};

    const int lrow = tid >> 2, lk4 = (tid & 3) * 4;
    const int wkk = tid >> 4, wcc = (tid & 15) * 4;

    int srcrow = 0;
    {
        int r = r0 + lrow;
        if (r < cnt) srcrow = g_list[e * CAP + r] / TOPK;  // token id
    }
    const float* xrow = x + (size_t)srcrow * H_DIM;

    for (int k0 = 0; k0 < H_DIM; k0 += BK) {
        float4 xa = *(const float4*)(xrow + k0 + lk4);
        Xs[lk4 + 0][lrow] = xa.x; Xs[lk4 + 1][lrow] = xa.y;
        Xs[lk4 + 2][lrow] = xa.z; Xs[lk4 + 3][lrow] = xa.w;
        *(float4*)&Wg[wkk][wcc] = *(const float4*)(W + (size_t)(k0 + wkk) * GUP_COLS + cb + wcc);
        *(float4*)&Wu[wkk][wcc] = *(const float4*)(W + (size_t)(k0 + wkk) * GUP_COLS + I_DIM + cb + wcc);
        __syncthreads();
#pragma unroll
        for (int kk = 0; kk < BK; kk++) {
            float a[4], bg[4], bu[4];
#pragma unroll
            for (int i = 0; i < 4; i++) a[i] = Xs[kk][ty * 4 + i];
#pragma unroll
            for (int j = 0; j < 4; j++) { bg[j] = Wg[kk][tx * 4 + j]; bu[j] = Wu[kk][tx * 4 + j]; }
#pragma unroll
            for (int i = 0; i < 4; i++)
#pragma unroll
                for (int j = 0; j < 4; j++) {
                    accG[i][j] += a[i] * bg[j];
                    accU[i][j] += a[i] * bu[j];
                }
        }
        __syncthreads();
    }
#pragma unroll
    for (int i = 0; i < 4; i++) {
        int r = r0 + ty * 4 + i;
        if (r < cnt) {
#pragma unroll
            for (int j = 0; j < 4; j++) {
                int c = cb + tx * 4 + j;
                float g = accG[i][j], u = accU[i][j];
                g_act_r[((size_t)e * CAP + r) * I_DIM + c] = (g / (1.f + expf(-g))) * u;
            }
        }
    }
}

// ----------------------- routed down -> ybuf[a, H] -------------------------
__global__ __launch_bounds__(256) void routed_down(
    const float* __restrict__ Wall /*[E,512,1024]*/)
{
    const int BK = 16;
    const int e = blockIdx.z;
    const int cnt = g_counts[e];
    const int r0 = blockIdx.y * 64;
    if (r0 >= cnt) return;

    __shared__ float Xs[BK][68];
    __shared__ float Ws[BK][64];
    const int tid = threadIdx.x;
    const int tx = tid & 15, ty = tid >> 4;
    const int cb = blockIdx.x * 64;
    const float* W = Wall + (size_t)e * I_DIM * H_DIM;

    float acc[4][4] = {};
    const int lrow = tid >> 2, lk4 = (tid & 3) * 4;
    const int wkk = tid >> 4, wcc = (tid & 15) * 4;
    const float* arow = g_act_r + ((size_t)e * CAP + (r0 + lrow)) * I_DIM;

    for (int k0 = 0; k0 < I_DIM; k0 += BK) {
        float4 xa = *(const float4*)(arow + k0 + lk4);
        Xs[lk4 + 0][lrow] = xa.x; Xs[lk4 + 1][lrow] = xa.y;
        Xs[lk4 + 2][lrow] = xa.z; Xs[lk4 + 3][lrow] = xa.w;
        *(float4*)&Ws[wkk][wcc] = *(const float4*)(W + (size_t)(k0 + wkk) * H_DIM + cb + wcc);
        __syncthreads();
#pragma unroll
        for (int kk = 0; kk < BK; kk++) {
            float a[4], b[4];
#pragma unroll
            for (int i = 0; i < 4; i++) a[i] = Xs[kk][ty * 4 + i];
#pragma unroll
            for (int j = 0; j < 4; j++) b[j] = Ws[kk][tx * 4 + j];
#pragma unroll
            for (int i = 0; i < 4; i++)
#pragma unroll
                for (int j = 0; j < 4; j++) acc[i][j] += a[i] * b[j];
        }
        __syncthreads();
    }
#pragma unroll
    for (int i = 0; i < 4; i++) {
        int r = r0 + ty * 4 + i;
        if (r < cnt) {
            int a = g_list[e * CAP + r];
#pragma unroll
            for (int j = 0; j < 4; j++)
                g_ybuf[(size_t)a * H_DIM + cb + tx * 4 + j] = acc[i][j];
        }
    }
}

// ------------------------------- combine -----------------------------------
__global__ __launch_bounds__(256) void combine_kernel(float* __restrict__ out)
{
    const int t = blockIdx.x;
    const int h4 = threadIdx.x * 4;
    float4 o = *(float4*)(out + (size_t)t * H_DIM + h4);
    float r0 = o.x, r1 = o.y, r2 = o.z, r3 = o.w;
#pragma unroll
    for (int k = 0; k < TOPK; k++) {
        int a = t * TOPK + k;
        if (g_keep[a]) {
            float wv = g_w[a] * SCALE_F;
            float4 y = *(const float4*)(g_ybuf + (size_t)a * H_DIM + h4);
            r0 += wv * y.x; r1 += wv * y.y; r2 += wv * y.z; r3 += wv * y.w;
        }
    }
    *(float4*)(out + (size_t)t * H_DIM + h4) = make_float4(r0, r1, r2, r3);
}

// ------------------------------- launcher ----------------------------------
extern "C" void kernel_launch(void* const* d_in, const int* in_sizes, int n_in,
                              void* d_out, int out_size)
{
    const float* x          = (const float*)d_in[0];
    const float* gate_w     = (const float*)d_in[1];
    const float* e_bias     = (const float*)d_in[2];
    const float* w_gate_up  = (const float*)d_in[3];
    const float* w_down     = (const float*)d_in[4];
    const float* ws_gate_up = (const float*)d_in[5];
    const float* ws_down    = (const float*)d_in[6];
    float* out = (float*)d_out;

    router_kernel<<<T_TOK, 256>>>(x, gate_w, e_bias);
    dispatch_kernel<<<E_EXP, 256>>>();
    shared_gateup<<<dim3(SH_ACT / 64, T_TOK / 64), 256>>>(x, ws_gate_up);
    shared_down<<<dim3(H_DIM / 64, T_TOK / 64), 256>>>(ws_down, out);
    routed_gateup<<<dim3(I_DIM / 64, CAP / 64, E_EXP), 256>>>(x, w_gate_up);
    routed_down<<<dim3(H_DIM / 64, CAP / 64, E_EXP), 256>>>(w_down);
    combine_kernel<<<T_TOK, 256>>>(out);
}

// round 2
// speedup vs baseline: 1.2491x; 1.2491x over previous
#include <cuda_runtime.h>
#include <cuda_bf16.h>
#include <math.h>

// ---------------------------------------------------------------------------
// DeepseekV2 MoE. GEMMs on tensor cores via mma.sync m16n8k16 bf16 with
// hi/lo split-precision (3 MMAs per logical fp32 MMA -> ~2^-18 rel accuracy).
// Pipeline: router -> dispatch -> shared_gateup -> shared_down(out) ->
//           routed_gateup -> routed_down -> combine.
// ---------------------------------------------------------------------------

#define T_TOK   1024
#define H_DIM   1024
#define E_EXP   64
#define I_DIM   512
#define TOPK    6
#define NGROUP  8
#define TKG     3
#define CAP     256
#define A_TOT   (T_TOK * TOPK)
#define SCALE_F 2.5f
#define GUP_COLS (2 * I_DIM)
#define SH_ACT   1024
#define SH_GUP   2048

#define LDA 18   // smem stride (elems) for 16-wide k tiles; conflict-free

// ------------------------------- scratch -----------------------------------
__device__ float g_w[A_TOT];
__device__ int   g_eidx[A_TOT];
__device__ int   g_counts[E_EXP];
__device__ int   g_list[E_EXP * CAP];
__device__ int   g_keep[A_TOT];
__device__ float g_act_s[T_TOK * SH_ACT];
__device__ float g_act_r[E_EXP * CAP * I_DIM];
__device__ float g_ybuf[A_TOT * H_DIM];

// ------------------------------- helpers -----------------------------------
__device__ __forceinline__ void f2hl(__nv_bfloat16* hp, __nv_bfloat16* lp, float x) {
    __nv_bfloat16 h = __float2bfloat16(x);
    *hp = h;
    *lp = __float2bfloat16(x - __bfloat162float(h));
}

__device__ __forceinline__ void mma_bf16(float c[4],
    unsigned a0, unsigned a1, unsigned a2, unsigned a3,
    unsigned b0, unsigned b1)
{
    asm volatile(
        "mma.sync.aligned.m16n8k16.row.col.f32.bf16.bf16.f32 "
        "{%0,%1,%2,%3}, {%4,%5,%6,%7}, {%8,%9}, {%0,%1,%2,%3};"
        : "+f"(c[0]), "+f"(c[1]), "+f"(c[2]), "+f"(c[3])
        : "r"(a0), "r"(a1), "r"(a2), "r"(a3), "r"(b0), "r"(b1));
}

__device__ __forceinline__ unsigned lds_u32(const __nv_bfloat16* p) {
    return *(const unsigned*)p;
}

// ------------------------------- router ------------------------------------
__global__ __launch_bounds__(256) void router_kernel(
    const float* __restrict__ x, const float* __restrict__ gw,
    const float* __restrict__ bias)
{
    __shared__ float xs[H_DIM];
    __shared__ float lg[E_EXP];
    const int t = blockIdx.x, tid = threadIdx.x;

    *(float4*)&xs[tid * 4] = *(const float4*)(x + (size_t)t * H_DIM + tid * 4);
    __syncthreads();

    if (tid < E_EXP) {
        float acc = 0.f;
#pragma unroll 8
        for (int h = 0; h < H_DIM; h++)
            acc += xs[h] * gw[h * E_EXP + tid];
        lg[tid] = acc;
    }
    __syncthreads();

    if (tid == 0) {
        float sc[E_EXP], s[E_EXP];
#pragma unroll
        for (int e = 0; e < E_EXP; e++) {
            sc[e] = 1.f / (1.f + expf(-lg[e]));
            s[e]  = sc[e] + bias[e];
        }
        float gs[NGROUP];
#pragma unroll
        for (int g = 0; g < NGROUP; g++) {
            float m1 = -INFINITY, m2 = -INFINITY;
            for (int j = 0; j < E_EXP / NGROUP; j++) {
                float v = s[g * (E_EXP / NGROUP) + j];
                if (v > m1) { m2 = m1; m1 = v; }
                else if (v > m2) { m2 = v; }
            }
            gs[g] = m1 + m2;
        }
        bool gsel[NGROUP];
#pragma unroll
        for (int g = 0; g < NGROUP; g++) gsel[g] = false;
        for (int it = 0; it < TKG; it++) {
            int bi = -1; float bv = -INFINITY;
            for (int g = 0; g < NGROUP; g++)
                if (!gsel[g] && gs[g] > bv) { bv = gs[g]; bi = g; }
            gsel[bi] = true;
        }
        bool used[E_EXP];
#pragma unroll
        for (int e = 0; e < E_EXP; e++) used[e] = false;
        int   idx[TOPK];
        float wv[TOPK];
        float wsum = 0.f;
        for (int k = 0; k < TOPK; k++) {
            int bi = -1; float bv = -INFINITY;
            for (int e = 0; e < E_EXP; e++) {
                if (!gsel[e / (E_EXP / NGROUP)] || used[e]) continue;
                if (s[e] > bv) { bv = s[e]; bi = e; }
            }
            used[bi] = true;
            idx[k] = bi;
            wv[k]  = sc[bi];
            wsum  += sc[bi];
        }
        float inv = 1.f / wsum;
        for (int k = 0; k < TOPK; k++) {
            g_w[t * TOPK + k]    = wv[k] * inv;
            g_eidx[t * TOPK + k] = idx[k];
        }
    }
}

// ------------------------------ dispatch -----------------------------------
__global__ __launch_bounds__(256) void dispatch_kernel()
{
    const int e = blockIdx.x, tid = threadIdx.x;
    const int lane = tid & 31, wid = tid >> 5;
    __shared__ int warp_tot[8];
    int base = 0;
    for (int chunk = 0; chunk < A_TOT; chunk += 256) {
        int a = chunk + tid;
        int m = (a < A_TOT && g_eidx[a] == e) ? 1 : 0;
        unsigned bal = __ballot_sync(0xffffffffu, m);
        if (lane == 0) warp_tot[wid] = __popc(bal);
        __syncthreads();
        int woff = 0, tot = 0;
#pragma unroll
        for (int i = 0; i < 8; i++) { if (i < wid) woff += warp_tot[i]; tot += warp_tot[i]; }
        if (m) {
            int pos = base + woff + __popc(bal & ((1u << lane) - 1u));
            if (pos < CAP) g_list[e * CAP + pos] = a;
            g_keep[a] = (pos < CAP) ? 1 : 0;
        }
        base += tot;
        __syncthreads();
    }
    if (tid == 0) g_counts[e] = base < CAP ? base : CAP;
}

// ===========================================================================
// Tensor-core GEMM kernels. Tile: 64x64, 256 thr = 8 warps (4M x 2N).
// Each warp: 16 rows x 32 cols (4 n-subtiles of 8). K-chunk = 16.
// ===========================================================================

// --------------------- shared gate_up (fused silu*mul) ---------------------
__global__ __launch_bounds__(256) void shared_gateup(
    const float* __restrict__ x, const float* __restrict__ W /*[H,2048]*/)
{
    __shared__ __nv_bfloat16 Ah[64 * LDA], Al[64 * LDA];
    __shared__ __nv_bfloat16 BgH[64 * LDA], BgL[64 * LDA];
    __shared__ __nv_bfloat16 BuH[64 * LDA], BuL[64 * LDA];

    const int tid = threadIdx.x;
    const int lane = tid & 31, wid = tid >> 5;
    const int gid = lane >> 2, tig = lane & 3;
    const int wm = wid & 3, wn = wid >> 2;
    const int rb = blockIdx.y * 64, cb = blockIdx.x * 64;

    float accG[4][4] = {}, accU[4][4] = {};

    const int arow = tid >> 2, ac4 = (tid & 3) * 4;
    const int bkk = tid >> 4, bc4 = (tid & 15) * 4;
    const float* xrow = x + (size_t)(rb + arow) * H_DIM + ac4;

    for (int k0 = 0; k0 < H_DIM; k0 += 16) {
        float4 va = *(const float4*)(xrow + k0);
        f2hl(&Ah[arow * LDA + ac4 + 0], &Al[arow * LDA + ac4 + 0], va.x);
        f2hl(&Ah[arow * LDA + ac4 + 1], &Al[arow * LDA + ac4 + 1], va.y);
        f2hl(&Ah[arow * LDA + ac4 + 2], &Al[arow * LDA + ac4 + 2], va.z);
        f2hl(&Ah[arow * LDA + ac4 + 3], &Al[arow * LDA + ac4 + 3], va.w);
        const float* wp = W + (size_t)(k0 + bkk) * SH_GUP + cb + bc4;
        float4 vg = *(const float4*)wp;
        float4 vu = *(const float4*)(wp + SH_ACT);
        f2hl(&BgH[(bc4 + 0) * LDA + bkk], &BgL[(bc4 + 0) * LDA + bkk], vg.x);
        f2hl(&BgH[(bc4 + 1) * LDA + bkk], &BgL[(bc4 + 1) * LDA + bkk], vg.y);
        f2hl(&BgH[(bc4 + 2) * LDA + bkk], &BgL[(bc4 + 2) * LDA + bkk], vg.z);
        f2hl(&BgH[(bc4 + 3) * LDA + bkk], &BgL[(bc4 + 3) * LDA + bkk], vg.w);
        f2hl(&BuH[(bc4 + 0) * LDA + bkk], &BuL[(bc4 + 0) * LDA + bkk], vu.x);
        f2hl(&BuH[(bc4 + 1) * LDA + bkk], &BuL[(bc4 + 1) * LDA + bkk], vu.y);
        f2hl(&BuH[(bc4 + 2) * LDA + bkk], &BuL[(bc4 + 2) * LDA + bkk], vu.z);
        f2hl(&BuH[(bc4 + 3) * LDA + bkk], &BuL[(bc4 + 3) * LDA + bkk], vu.w);
        __syncthreads();

        const int ar = (wm * 16 + gid) * LDA + tig * 2;
        unsigned ah0 = lds_u32(&Ah[ar]),            ah1 = lds_u32(&Ah[ar + 8 * LDA]);
        unsigned ah2 = lds_u32(&Ah[ar + 8]),        ah3 = lds_u32(&Ah[ar + 8 * LDA + 8]);
        unsigned al0 = lds_u32(&Al[ar]),            al1 = lds_u32(&Al[ar + 8 * LDA]);
        unsigned al2 = lds_u32(&Al[ar + 8]),        al3 = lds_u32(&Al[ar + 8 * LDA + 8]);
#pragma unroll
        for (int nt = 0; nt < 4; nt++) {
            const int br = (wn * 32 + nt * 8 + gid) * LDA + tig * 2;
            unsigned gh0 = lds_u32(&BgH[br]), gh1 = lds_u32(&BgH[br + 8]);
            unsigned gl0 = lds_u32(&BgL[br]), gl1 = lds_u32(&BgL[br + 8]);
            mma_bf16(accG[nt], ah0, ah1, ah2, ah3, gh0, gh1);
            mma_bf16(accG[nt], ah0, ah1, ah2, ah3, gl0, gl1);
            mma_bf16(accG[nt], al0, al1, al2, al3, gh0, gh1);
            unsigned uh0 = lds_u32(&BuH[br]), uh1 = lds_u32(&BuH[br + 8]);
            unsigned ul0 = lds_u32(&BuL[br]), ul1 = lds_u32(&BuL[br + 8]);
            mma_bf16(accU[nt], ah0, ah1, ah2, ah3, uh0, uh1);
            mma_bf16(accU[nt], ah0, ah1, ah2, ah3, ul0, ul1);
            mma_bf16(accU[nt], al0, al1, al2, al3, uh0, uh1);
        }
        __syncthreads();
    }
    const int r0 = rb + wm * 16 + gid;
#pragma unroll
    for (int nt = 0; nt < 4; nt++) {
        const int c = cb + wn * 32 + nt * 8 + tig * 2;
#pragma unroll
        for (int i = 0; i < 2; i++) {
            float g0 = accG[nt][i * 2 + 0], u0 = accU[nt][i * 2 + 0];
            float g1 = accG[nt][i * 2 + 1], u1 = accU[nt][i * 2 + 1];
            int r = r0 + i * 8;
            g_act_s[(size_t)r * SH_ACT + c + 0] = (g0 / (1.f + expf(-g0))) * u0;
            g_act_s[(size_t)r * SH_ACT + c + 1] = (g1 / (1.f + expf(-g1))) * u1;
        }
    }
}

// ----------------------- shared down (writes out) --------------------------
__global__ __launch_bounds__(256) void shared_down(
    const float* __restrict__ W /*[1024,1024]*/, float* __restrict__ out)
{
    __shared__ __nv_bfloat16 Ah[64 * LDA], Al[64 * LDA];
    __shared__ __nv_bfloat16 BH[64 * LDA], BL[64 * LDA];

    const int tid = threadIdx.x;
    const int lane = tid & 31, wid = tid >> 5;
    const int gid = lane >> 2, tig = lane & 3;
    const int wm = wid & 3, wn = wid >> 2;
    const int rb = blockIdx.y * 64, cb = blockIdx.x * 64;

    float acc[4][4] = {};
    const int arow = tid >> 2, ac4 = (tid & 3) * 4;
    const int bkk = tid >> 4, bc4 = (tid & 15) * 4;
    const float* xrow = g_act_s + (size_t)(rb + arow) * SH_ACT + ac4;

    for (int k0 = 0; k0 < SH_ACT; k0 += 16) {
        float4 va = *(const float4*)(xrow + k0);
        f2hl(&Ah[arow * LDA + ac4 + 0], &Al[arow * LDA + ac4 + 0], va.x);
        f2hl(&Ah[arow * LDA + ac4 + 1], &Al[arow * LDA + ac4 + 1], va.y);
        f2hl(&Ah[arow * LDA + ac4 + 2], &Al[arow * LDA + ac4 + 2], va.z);
        f2hl(&Ah[arow * LDA + ac4 + 3], &Al[arow * LDA + ac4 + 3], va.w);
        float4 vb = *(const float4*)(W + (size_t)(k0 + bkk) * H_DIM + cb + bc4);
        f2hl(&BH[(bc4 + 0) * LDA + bkk], &BL[(bc4 + 0) * LDA + bkk], vb.x);
        f2hl(&BH[(bc4 + 1) * LDA + bkk], &BL[(bc4 + 1) * LDA + bkk], vb.y);
        f2hl(&BH[(bc4 + 2) * LDA + bkk], &BL[(bc4 + 2) * LDA + bkk], vb.z);
        f2hl(&BH[(bc4 + 3) * LDA + bkk], &BL[(bc4 + 3) * LDA + bkk], vb.w);
        __syncthreads();

        const int ar = (wm * 16 + gid) * LDA + tig * 2;
        unsigned ah0 = lds_u32(&Ah[ar]),     ah1 = lds_u32(&Ah[ar + 8 * LDA]);
        unsigned ah2 = lds_u32(&Ah[ar + 8]), ah3 = lds_u32(&Ah[ar + 8 * LDA + 8]);
        unsigned al0 = lds_u32(&Al[ar]),     al1 = lds_u32(&Al[ar + 8 * LDA]);
        unsigned al2 = lds_u32(&Al[ar + 8]), al3 = lds_u32(&Al[ar + 8 * LDA + 8]);
#pragma unroll
        for (int nt = 0; nt < 4; nt++) {
            const int br = (wn * 32 + nt * 8 + gid) * LDA + tig * 2;
            unsigned bh0 = lds_u32(&BH[br]), bh1 = lds_u32(&BH[br + 8]);
            unsigned bl0 = lds_u32(&BL[br]), bl1 = lds_u32(&BL[br + 8]);
            mma_bf16(acc[nt], ah0, ah1, ah2, ah3, bh0, bh1);
            mma_bf16(acc[nt], ah0, ah1, ah2, ah3, bl0, bl1);
            mma_bf16(acc[nt], al0, al1, al2, al3, bh0, bh1);
        }
        __syncthreads();
    }
    const int r0 = rb + wm * 16 + gid;
#pragma unroll
    for (int nt = 0; nt < 4; nt++) {
        const int c = cb + wn * 32 + nt * 8 + tig * 2;
        out[(size_t)(r0    ) * H_DIM + c + 0] = acc[nt][0];
        out[(size_t)(r0    ) * H_DIM + c + 1] = acc[nt][1];
        out[(size_t)(r0 + 8) * H_DIM + c + 0] = acc[nt][2];
        out[(size_t)(r0 + 8) * H_DIM + c + 1] = acc[nt][3];
    }
}

// -------------------- routed gate_up (gathered rows) -----------------------
__global__ __launch_bounds__(256) void routed_gateup(
    const float* __restrict__ x, const float* __restrict__ Wall /*[E,H,1024]*/)
{
    const int e = blockIdx.z;
    const int cnt = g_counts[e];
    const int r0b = blockIdx.y * 64;
    if (r0b >= cnt) return;

    __shared__ __nv_bfloat16 Ah[64 * LDA], Al[64 * LDA];
    __shared__ __nv_bfloat16 BgH[64 * LDA], BgL[64 * LDA];
    __shared__ __nv_bfloat16 BuH[64 * LDA], BuL[64 * LDA];

    const int tid = threadIdx.x;
    const int lane = tid & 31, wid = tid >> 5;
    const int gid = lane >> 2, tig = lane & 3;
    const int wm = wid & 3, wn = wid >> 2;
    const int cb = blockIdx.x * 64;
    const float* W = Wall + (size_t)e * H_DIM * GUP_COLS;

    float accG[4][4] = {}, accU[4][4] = {};

    const int arow = tid >> 2, ac4 = (tid & 3) * 4;
    const int bkk = tid >> 4, bc4 = (tid & 15) * 4;

    int srcrow = 0;
    {
        int r = r0b + arow;
        if (r < cnt) srcrow = g_list[e * CAP + r] / TOPK;
    }
    const float* xrow = x + (size_t)srcrow * H_DIM + ac4;

    for (int k0 = 0; k0 < H_DIM; k0 += 16) {
        float4 va = *(const float4*)(xrow + k0);
        f2hl(&Ah[arow * LDA + ac4 + 0], &Al[arow * LDA + ac4 + 0], va.x);
        f2hl(&Ah[arow * LDA + ac4 + 1], &Al[arow * LDA + ac4 + 1], va.y);
        f2hl(&Ah[arow * LDA + ac4 + 2], &Al[arow * LDA + ac4 + 2], va.z);
        f2hl(&Ah[arow * LDA + ac4 + 3], &Al[arow * LDA + ac4 + 3], va.w);
        const float* wp = W + (size_t)(k0 + bkk) * GUP_COLS + cb + bc4;
        float4 vg = *(const float4*)wp;
        float4 vu = *(const float4*)(wp + I_DIM);
        f2hl(&BgH[(bc4 + 0) * LDA + bkk], &BgL[(bc4 + 0) * LDA + bkk], vg.x);
        f2hl(&BgH[(bc4 + 1) * LDA + bkk], &BgL[(bc4 + 1) * LDA + bkk], vg.y);
        f2hl(&BgH[(bc4 + 2) * LDA + bkk], &BgL[(bc4 + 2) * LDA + bkk], vg.z);
        f2hl(&BgH[(bc4 + 3) * LDA + bkk], &BgL[(bc4 + 3) * LDA + bkk], vg.w);
        f2hl(&BuH[(bc4 + 0) * LDA + bkk], &BuL[(bc4 + 0) * LDA + bkk], vu.x);
        f2hl(&BuH[(bc4 + 1) * LDA + bkk], &BuL[(bc4 + 1) * LDA + bkk], vu.y);
        f2hl(&BuH[(bc4 + 2) * LDA + bkk], &BuL[(bc4 + 2) * LDA + bkk], vu.z);
        f2hl(&BuH[(bc4 + 3) * LDA + bkk], &BuL[(bc4 + 3) * LDA + bkk], vu.w);
        __syncthreads();

        const int ar = (wm * 16 + gid) * LDA + tig * 2;
        unsigned ah0 = lds_u32(&Ah[ar]),     ah1 = lds_u32(&Ah[ar + 8 * LDA]);
        unsigned ah2 = lds_u32(&Ah[ar + 8]), ah3 = lds_u32(&Ah[ar + 8 * LDA + 8]);
        unsigned al0 = lds_u32(&Al[ar]),     al1 = lds_u32(&Al[ar + 8 * LDA]);
        unsigned al2 = lds_u32(&Al[ar + 8]), al3 = lds_u32(&Al[ar + 8 * LDA + 8]);
#pragma unroll
        for (int nt = 0; nt < 4; nt++) {
            const int br = (wn * 32 + nt * 8 + gid) * LDA + tig * 2;
            unsigned gh0 = lds_u32(&BgH[br]), gh1 = lds_u32(&BgH[br + 8]);
            unsigned gl0 = lds_u32(&BgL[br]), gl1 = lds_u32(&BgL[br + 8]);
            mma_bf16(accG[nt], ah0, ah1, ah2, ah3, gh0, gh1);
            mma_bf16(accG[nt], ah0, ah1, ah2, ah3, gl0, gl1);
            mma_bf16(accG[nt], al0, al1, al2, al3, gh0, gh1);
            unsigned uh0 = lds_u32(&BuH[br]), uh1 = lds_u32(&BuH[br + 8]);
            unsigned ul0 = lds_u32(&BuL[br]), ul1 = lds_u32(&BuL[br + 8]);
            mma_bf16(accU[nt], ah0, ah1, ah2, ah3, uh0, uh1);
            mma_bf16(accU[nt], ah0, ah1, ah2, ah3, ul0, ul1);
            mma_bf16(accU[nt], al0, al1, al2, al3, uh0, uh1);
        }
        __syncthreads();
    }
    const int rw = wm * 16 + gid;
#pragma unroll
    for (int nt = 0; nt < 4; nt++) {
        const int c = cb + wn * 32 + nt * 8 + tig * 2;
#pragma unroll
        for (int i = 0; i < 2; i++) {
            int r = r0b + rw + i * 8;
            if (r < cnt) {
                float g0 = accG[nt][i * 2 + 0], u0 = accU[nt][i * 2 + 0];
                float g1 = accG[nt][i * 2 + 1], u1 = accU[nt][i * 2 + 1];
                g_act_r[((size_t)e * CAP + r) * I_DIM + c + 0] = (g0 / (1.f + expf(-g0))) * u0;
                g_act_r[((size_t)e * CAP + r) * I_DIM + c + 1] = (g1 / (1.f + expf(-g1))) * u1;
            }
        }
    }
}

// ----------------------- routed down -> ybuf[a, H] -------------------------
__global__ __launch_bounds__(256) void routed_down(
    const float* __restrict__ Wall /*[E,512,1024]*/)
{
    const int e = blockIdx.z;
    const int cnt = g_counts[e];
    const int r0b = blockIdx.y * 64;
    if (r0b >= cnt) return;

    __shared__ __nv_bfloat16 Ah[64 * LDA], Al[64 * LDA];
    __shared__ __nv_bfloat16 BH[64 * LDA], BL[64 * LDA];

    const int tid = threadIdx.x;
    const int lane = tid & 31, wid = tid >> 5;
    const int gid = lane >> 2, tig = lane & 3;
    const int wm = wid & 3, wn = wid >> 2;
    const int cb = blockIdx.x * 64;
    const float* W = Wall + (size_t)e * I_DIM * H_DIM;

    float acc[4][4] = {};
    const int arow = tid >> 2, ac4 = (tid & 3) * 4;
    const int bkk = tid >> 4, bc4 = (tid & 15) * 4;
    const float* xrow = g_act_r + ((size_t)e * CAP + (r0b + arow)) * I_DIM + ac4;

    for (int k0 = 0; k0 < I_DIM; k0 += 16) {
        float4 va = *(const float4*)(xrow + k0);
        f2hl(&Ah[arow * LDA + ac4 + 0], &Al[arow * LDA + ac4 + 0], va.x);
        f2hl(&Ah[arow * LDA + ac4 + 1], &Al[arow * LDA + ac4 + 1], va.y);
        f2hl(&Ah[arow * LDA + ac4 + 2], &Al[arow * LDA + ac4 + 2], va.z);
        f2hl(&Ah[arow * LDA + ac4 + 3], &Al[arow * LDA + ac4 + 3], va.w);
        float4 vb = *(const float4*)(W + (size_t)(k0 + bkk) * H_DIM + cb + bc4);
        f2hl(&BH[(bc4 + 0) * LDA + bkk], &BL[(bc4 + 0) * LDA + bkk], vb.x);
        f2hl(&BH[(bc4 + 1) * LDA + bkk], &BL[(bc4 + 1) * LDA + bkk], vb.y);
        f2hl(&BH[(bc4 + 2) * LDA + bkk], &BL[(bc4 + 2) * LDA + bkk], vb.z);
        f2hl(&BH[(bc4 + 3) * LDA + bkk], &BL[(bc4 + 3) * LDA + bkk], vb.w);
        __syncthreads();

        const int ar = (wm * 16 + gid) * LDA + tig * 2;
        unsigned ah0 = lds_u32(&Ah[ar]),     ah1 = lds_u32(&Ah[ar + 8 * LDA]);
        unsigned ah2 = lds_u32(&Ah[ar + 8]), ah3 = lds_u32(&Ah[ar + 8 * LDA + 8]);
        unsigned al0 = lds_u32(&Al[ar]),     al1 = lds_u32(&Al[ar + 8 * LDA]);
        unsigned al2 = lds_u32(&Al[ar + 8]), al3 = lds_u32(&Al[ar + 8 * LDA + 8]);
#pragma unroll
        for (int nt = 0; nt < 4; nt++) {
            const int br = (wn * 32 + nt * 8 + gid) * LDA + tig * 2;
            unsigned bh0 = lds_u32(&BH[br]), bh1 = lds_u32(&BH[br + 8]);
            unsigned bl0 = lds_u32(&BL[br]), bl1 = lds_u32(&BL[br + 8]);
            mma_bf16(acc[nt], ah0, ah1, ah2, ah3, bh0, bh1);
            mma_bf16(acc[nt], ah0, ah1, ah2, ah3, bl0, bl1);
            mma_bf16(acc[nt], al0, al1, al2, al3, bh0, bh1);
        }
        __syncthreads();
    }
    const int rw = wm * 16 + gid;
#pragma unroll
    for (int nt = 0; nt < 4; nt++) {
        const int c = cb + wn * 32 + nt * 8 + tig * 2;
#pragma unroll
        for (int i = 0; i < 2; i++) {
            int r = r0b + rw + i * 8;
            if (r < cnt) {
                int a = g_list[e * CAP + r];
                g_ybuf[(size_t)a * H_DIM + c + 0] = acc[nt][i * 2 + 0];
                g_ybuf[(size_t)a * H_DIM + c + 1] = acc[nt][i * 2 + 1];
            }
        }
    }
}

// ------------------------------- combine -----------------------------------
__global__ __launch_bounds__(256) void combine_kernel(float* __restrict__ out)
{
    const int t = blockIdx.x;
    const int h4 = threadIdx.x * 4;
    float4 o = *(float4*)(out + (size_t)t * H_DIM + h4);
    float r0 = o.x, r1 = o.y, r2 = o.z, r3 = o.w;
#pragma unroll
    for (int k = 0; k < TOPK; k++) {
        int a = t * TOPK + k;
        if (g_keep[a]) {
            float wv = g_w[a] * SCALE_F;
            float4 y = *(const float4*)(g_ybuf + (size_t)a * H_DIM + h4);
            r0 += wv * y.x; r1 += wv * y.y; r2 += wv * y.z; r3 += wv * y.w;
        }
    }
    *(float4*)(out + (size_t)t * H_DIM + h4) = make_float4(r0, r1, r2, r3);
}

// ------------------------------- launcher ----------------------------------
extern "C" void kernel_launch(void* const* d_in, const int* in_sizes, int n_in,
                              void* d_out, int out_size)
{
    const float* x          = (const float*)d_in[0];
    const float* gate_w     = (const float*)d_in[1];
    const float* e_bias     = (const float*)d_in[2];
    const float* w_gate_up  = (const float*)d_in[3];
    const float* w_down     = (const float*)d_in[4];
    const float* ws_gate_up = (const float*)d_in[5];
    const float* ws_down    = (const float*)d_in[6];
    float* out = (float*)d_out;

    router_kernel<<<T_TOK, 256>>>(x, gate_w, e_bias);
    dispatch_kernel<<<E_EXP, 256>>>();
    shared_gateup<<<dim3(SH_ACT / 64, T_TOK / 64), 256>>>(x, ws_gate_up);
    shared_down<<<dim3(H_DIM / 64, T_TOK / 64), 256>>>(ws_down, out);
    routed_gateup<<<dim3(I_DIM / 64, CAP / 64, E_EXP), 256>>>(x, w_gate_up);
    routed_down<<<dim3(H_DIM / 64, CAP / 64, E_EXP), 256>>>(w_down);
    combine_kernel<<<T_TOK, 256>>>(out);
}

// round 5
// speedup vs baseline: 1.4963x; 1.1979x over previous
#include <cuda_runtime.h>
#include <cuda_bf16.h>
#include <cstdint>
#include <math.h>

// ---------------------------------------------------------------------------
// DeepseekV2 MoE. Strategy:
//  - One-time split of x + all weights into bf16 hi/lo planes (streaming).
//  - GEMMs: m16n8k16 bf16 MMA, 3-term hi/lo split; fragments via ldmatrix
//    (A: .x4 from [m][k] planes, B: .x4.trans from [k][n] planes).
//  - Gate_up epilogues emit activations directly as hi/lo planes.
// ---------------------------------------------------------------------------

#define T_TOK   1024
#define H_DIM   1024
#define E_EXP   64
#define I_DIM   512
#define TOPK    6
#define NGROUP  8
#define TKG     3
#define CAP     256
#define A_TOT   (T_TOK * TOPK)
#define SCALE_F 2.5f
#define GUP_COLS (2 * I_DIM)
#define SH_ACT   1024
#define SH_GUP   2048

#define KC 32          // k-chunk
#define SA 40          // A smem stride (32 + 8 pad) -> conflict-free ldmatrix
#define SB 72          // B smem stride (64 + 8 pad) -> conflict-free ldmatrix.trans

// ------------------------------- scratch -----------------------------------
__device__ float g_w[A_TOT];
__device__ int   g_eidx[A_TOT];
__device__ int   g_counts[E_EXP];
__device__ int   g_list[E_EXP * CAP];
__device__ int   g_keep[A_TOT];

__device__ __nv_bfloat16 g_xs_h[T_TOK * H_DIM];
__device__ __nv_bfloat16 g_xs_l[T_TOK * H_DIM];
__device__ __nv_bfloat16 g_wsgu_h[H_DIM * SH_GUP];
__device__ __nv_bfloat16 g_wsgu_l[H_DIM * SH_GUP];
__device__ __nv_bfloat16 g_wsd_h[SH_ACT * H_DIM];
__device__ __nv_bfloat16 g_wsd_l[SH_ACT * H_DIM];
__device__ __nv_bfloat16 g_wgu_h[(size_t)E_EXP * H_DIM * GUP_COLS];
__device__ __nv_bfloat16 g_wgu_l[(size_t)E_EXP * H_DIM * GUP_COLS];
__device__ __nv_bfloat16 g_wd_h[(size_t)E_EXP * I_DIM * H_DIM];
__device__ __nv_bfloat16 g_wd_l[(size_t)E_EXP * I_DIM * H_DIM];
__device__ __nv_bfloat16 g_acts_h[T_TOK * SH_ACT];
__device__ __nv_bfloat16 g_acts_l[T_TOK * SH_ACT];
__device__ __nv_bfloat16 g_actr_h[(size_t)E_EXP * CAP * I_DIM];
__device__ __nv_bfloat16 g_actr_l[(size_t)E_EXP * CAP * I_DIM];
__device__ float g_ybuf[(size_t)A_TOT * H_DIM];

// ------------------------------- helpers -----------------------------------
__device__ __forceinline__ unsigned pack2(__nv_bfloat16 a, __nv_bfloat16 b) {
    __nv_bfloat162 t = __halves2bfloat162(a, b);
    return *(unsigned*)&t;
}

__device__ __forceinline__ void mma_bf16(float c[4],
    unsigned a0, unsigned a1, unsigned a2, unsigned a3,
    unsigned b0, unsigned b1)
{
    asm volatile(
        "mma.sync.aligned.m16n8k16.row.col.f32.bf16.bf16.f32 "
        "{%0,%1,%2,%3}, {%4,%5,%6,%7}, {%8,%9}, {%0,%1,%2,%3};"
        : "+f"(c[0]), "+f"(c[1]), "+f"(c[2]), "+f"(c[3])
        : "r"(a0), "r"(a1), "r"(a2), "r"(a3), "r"(b0), "r"(b1));
}

__device__ __forceinline__ void ldsm4(unsigned* r, uint32_t addr) {
    asm volatile("ldmatrix.sync.aligned.m8n8.x4.shared.b16 {%0,%1,%2,%3}, [%4];"
        : "=r"(r[0]), "=r"(r[1]), "=r"(r[2]), "=r"(r[3]) : "r"(addr));
}
__device__ __forceinline__ void ldsm4t(unsigned* r, uint32_t addr) {
    asm volatile("ldmatrix.sync.aligned.m8n8.x4.trans.shared.b16 {%0,%1,%2,%3}, [%4];"
        : "=r"(r[0]), "=r"(r[1]), "=r"(r[2]), "=r"(r[3]) : "r"(addr));
}

// ------------------------------- split -------------------------------------
__global__ __launch_bounds__(256) void split_kernel(
    const float4* __restrict__ src, uint2* __restrict__ hi, uint2* __restrict__ lo, int n4)
{
    int i = blockIdx.x * 256 + threadIdx.x;
    if (i >= n4) return;
    float4 v = src[i];
    __nv_bfloat16 h0 = __float2bfloat16(v.x), h1 = __float2bfloat16(v.y);
    __nv_bfloat16 h2 = __float2bfloat16(v.z), h3 = __float2bfloat16(v.w);
    __nv_bfloat16 l0 = __float2bfloat16(v.x - __bfloat162float(h0));
    __nv_bfloat16 l1 = __float2bfloat16(v.y - __bfloat162float(h1));
    __nv_bfloat16 l2 = __float2bfloat16(v.z - __bfloat162float(h2));
    __nv_bfloat16 l3 = __float2bfloat16(v.w - __bfloat162float(h3));
    hi[i] = make_uint2(pack2(h0, h1), pack2(h2, h3));
    lo[i] = make_uint2(pack2(l0, l1), pack2(l2, l3));
}

// ------------------------------- router ------------------------------------
__global__ __launch_bounds__(256) void router_kernel(
    const float* __restrict__ x, const float* __restrict__ gw,
    const float* __restrict__ bias)
{
    __shared__ float xs[H_DIM];
    __shared__ float lg[E_EXP];
    const int t = blockIdx.x, tid = threadIdx.x;

    *(float4*)&xs[tid * 4] = *(const float4*)(x + (size_t)t * H_DIM + tid * 4);
    __syncthreads();

    if (tid < E_EXP) {
        float acc = 0.f;
#pragma unroll 8
        for (int h = 0; h < H_DIM; h++)
            acc += xs[h] * gw[h * E_EXP + tid];
        lg[tid] = acc;
    }
    __syncthreads();

    if (tid == 0) {
        float sc[E_EXP], s[E_EXP];
#pragma unroll
        for (int e = 0; e < E_EXP; e++) {
            sc[e] = 1.f / (1.f + expf(-lg[e]));
            s[e]  = sc[e] + bias[e];
        }
        float gs[NGROUP];
#pragma unroll
        for (int g = 0; g < NGROUP; g++) {
            float m1 = -INFINITY, m2 = -INFINITY;
            for (int j = 0; j < E_EXP / NGROUP; j++) {
                float v = s[g * (E_EXP / NGROUP) + j];
                if (v > m1) { m2 = m1; m1 = v; }
                else if (v > m2) { m2 = v; }
            }
            gs[g] = m1 + m2;
        }
        bool gsel[NGROUP];
#pragma unroll
        for (int g = 0; g < NGROUP; g++) gsel[g] = false;
        for (int it = 0; it < TKG; it++) {
            int bi = -1; float bv = -INFINITY;
            for (int g = 0; g < NGROUP; g++)
                if (!gsel[g] && gs[g] > bv) { bv = gs[g]; bi = g; }
            gsel[bi] = true;
        }
        bool used[E_EXP];
#pragma unroll
        for (int e = 0; e < E_EXP; e++) used[e] = false;
        int   idx[TOPK];
        float wv[TOPK];
        float wsum = 0.f;
        for (int k = 0; k < TOPK; k++) {
            int bi = -1; float bv = -INFINITY;
            for (int e = 0; e < E_EXP; e++) {
                if (!gsel[e / (E_EXP / NGROUP)] || used[e]) continue;
                if (s[e] > bv) { bv = s[e]; bi = e; }
            }
            used[bi] = true;
            idx[k] = bi;
            wv[k]  = sc[bi];
            wsum  += sc[bi];
        }
        float inv = 1.f / wsum;
        for (int k = 0; k < TOPK; k++) {
            g_w[t * TOPK + k]    = wv[k] * inv;
            g_eidx[t * TOPK + k] = idx[k];
        }
    }
}

// ------------------------------ dispatch -----------------------------------
__global__ __launch_bounds__(256) void dispatch_kernel()
{
    const int e = blockIdx.x, tid = threadIdx.x;
    const int lane = tid & 31, wid = tid >> 5;
    __shared__ int warp_tot[8];
    int base = 0;
    for (int chunk = 0; chunk < A_TOT; chunk += 256) {
        int a = chunk + tid;
        int m = (a < A_TOT && g_eidx[a] == e) ? 1 : 0;
        unsigned bal = __ballot_sync(0xffffffffu, m);
        if (lane == 0) warp_tot[wid] = __popc(bal);
        __syncthreads();
        int woff = 0, tot = 0;
#pragma unroll
        for (int i = 0; i < 8; i++) { if (i < wid) woff += warp_tot[i]; tot += warp_tot[i]; }
        if (m) {
            int pos = base + woff + __popc(bal & ((1u << lane) - 1u));
            if (pos < CAP) g_list[e * CAP + pos] = a;
            g_keep[a] = (pos < CAP) ? 1 : 0;
        }
        base += tot;
        __syncthreads();
    }
    if (tid == 0) g_counts[e] = base < CAP ? base : CAP;
}

// ===========================================================================
// GEMM kernels: 64x64 tile, 256 thr = 8 warps (4M x 2N), warp = 16x32.
// ===========================================================================

// --------------------- shared gate_up -> act planes ------------------------
__global__ __launch_bounds__(256) void shared_gateup_tc()
{
    __shared__ __align__(16) __nv_bfloat16 sAh[64 * SA], sAl[64 * SA];
    __shared__ __align__(16) __nv_bfloat16 sGh[KC * SB], sGl[KC * SB];
    __shared__ __align__(16) __nv_bfloat16 sUh[KC * SB], sUl[KC * SB];

    const int tid = threadIdx.x, lane = tid & 31, wid = tid >> 5;
    const int gid = lane >> 2, tig = lane & 3;
    const int wm = wid & 3, wn = wid >> 2;
    const int rb = blockIdx.y * 64, cb = blockIdx.x * 64;

    const int ar = tid >> 2, ac8 = (tid & 3) * 8;
    const int bk = tid >> 3, bn8 = (tid & 7) * 8;

    const __nv_bfloat16* aH = g_xs_h + (size_t)(rb + ar) * H_DIM + ac8;
    const __nv_bfloat16* aL = g_xs_l + (size_t)(rb + ar) * H_DIM + ac8;
    const __nv_bfloat16* gH = g_wsgu_h + (size_t)bk * SH_GUP + cb + bn8;
    const __nv_bfloat16* gL = g_wsgu_l + (size_t)bk * SH_GUP + cb + bn8;
    const __nv_bfloat16* uH = gH + SH_ACT;
    const __nv_bfloat16* uL = gL + SH_ACT;

    const uint32_t aBase = (uint32_t)((((wm * 16 + (lane & 15)) * SA) + (lane >> 4) * 8) * 2);
    uint32_t aOffH = (uint32_t)__cvta_generic_to_shared(sAh) + aBase;
    uint32_t aOffL = (uint32_t)__cvta_generic_to_shared(sAl) + aBase;
    const int mB = lane >> 3;
    const uint32_t bBase = (uint32_t)(((((mB & 1) * 8 + (lane & 7)) * SB) + wn * 32 + (mB >> 1) * 8) * 2);
    uint32_t gOffH = (uint32_t)__cvta_generic_to_shared(sGh) + bBase;
    uint32_t gOffL = (uint32_t)__cvta_generic_to_shared(sGl) + bBase;
    uint32_t uOffH = (uint32_t)__cvta_generic_to_shared(sUh) + bBase;
    uint32_t uOffL = (uint32_t)__cvta_generic_to_shared(sUl) + bBase;

    float accG[4][4] = {}, accU[4][4] = {};

    for (int k0 = 0; k0 < H_DIM; k0 += KC) {
        *(uint4*)&sAh[ar * SA + ac8] = *(const uint4*)(aH + k0);
        *(uint4*)&sAl[ar * SA + ac8] = *(const uint4*)(aL + k0);
        *(uint4*)&sGh[bk * SB + bn8] = *(const uint4*)(gH + (size_t)k0 * SH_GUP);
        *(uint4*)&sGl[bk * SB + bn8] = *(const uint4*)(gL + (size_t)k0 * SH_GUP);
        *(uint4*)&sUh[bk * SB + bn8] = *(const uint4*)(uH + (size_t)k0 * SH_GUP);
        *(uint4*)&sUl[bk * SB + bn8] = *(const uint4*)(uL + (size_t)k0 * SH_GUP);
        __syncthreads();
#pragma unroll
        for (int s = 0; s < 2; s++) {
            unsigned ah[4], al[4];
            ldsm4(ah, aOffH + s * 32);
            ldsm4(al, aOffL + s * 32);
            unsigned gh[8], gl[8], uh[8], ul[8];
#pragma unroll
            for (int g = 0; g < 2; g++) {
                uint32_t off = (uint32_t)(s * 16 * SB) * 2 + g * 32;
                ldsm4t(&gh[g * 4], gOffH + off);
                ldsm4t(&gl[g * 4], gOffL + off);
                ldsm4t(&uh[g * 4], uOffH + off);
                ldsm4t(&ul[g * 4], uOffL + off);
            }
#pragma unroll
            for (int t = 0; t < 4; t++) {
                int p = (t >> 1) * 4 + (t & 1) * 2;
                mma_bf16(accG[t], ah[0], ah[1], ah[2], ah[3], gh[p], gh[p + 1]);
                mma_bf16(accG[t], ah[0], ah[1], ah[2], ah[3], gl[p], gl[p + 1]);
                mma_bf16(accG[t], al[0], al[1], al[2], al[3], gh[p], gh[p + 1]);
                mma_bf16(accU[t], ah[0], ah[1], ah[2], ah[3], uh[p], uh[p + 1]);
                mma_bf16(accU[t], ah[0], ah[1], ah[2], ah[3], ul[p], ul[p + 1]);
                mma_bf16(accU[t], al[0], al[1], al[2], al[3], uh[p], uh[p + 1]);
            }
        }
        __syncthreads();
    }
    const int r0 = rb + wm * 16 + gid;
#pragma unroll
    for (int t = 0; t < 4; t++) {
        int c = cb + wn * 32 + t * 8 + tig * 2;
#pragma unroll
        for (int i = 0; i < 2; i++) {
            int r = r0 + i * 8;
            float g0 = accG[t][i * 2], u0 = accU[t][i * 2];
            float g1 = accG[t][i * 2 + 1], u1 = accU[t][i * 2 + 1];
            float a0 = (g0 / (1.f + expf(-g0))) * u0;
            float a1 = (g1 / (1.f + expf(-g1))) * u1;
            __nv_bfloat16 h0 = __float2bfloat16(a0), h1 = __float2bfloat16(a1);
            __nv_bfloat16 l0 = __float2bfloat16(a0 - __bfloat162float(h0));
            __nv_bfloat16 l1 = __float2bfloat16(a1 - __bfloat162float(h1));
            *(unsigned*)&g_acts_h[(size_t)r * SH_ACT + c] = pack2(h0, h1);
            *(unsigned*)&g_acts_l[(size_t)r * SH_ACT + c] = pack2(l0, l1);
        }
    }
}

// ----------------------- shared down (writes out) --------------------------
__global__ __launch_bounds__(256) void shared_down_tc(float* __restrict__ out)
{
    __shared__ __align__(16) __nv_bfloat16 sAh[64 * SA], sAl[64 * SA];
    __shared__ __align__(16) __nv_bfloat16 sBh[KC * SB], sBl[KC * SB];

    const int tid = threadIdx.x, lane = tid & 31, wid = tid >> 5;
    const int gid = lane >> 2, tig = lane & 3;
    const int wm = wid & 3, wn = wid >> 2;
    const int rb = blockIdx.y * 64, cb = blockIdx.x * 64;

    const int ar = tid >> 2, ac8 = (tid & 3) * 8;
    const int bk = tid >> 3, bn8 = (tid & 7) * 8;

    const __nv_bfloat16* aH = g_acts_h + (size_t)(rb + ar) * SH_ACT + ac8;
    const __nv_bfloat16* aL = g_acts_l + (size_t)(rb + ar) * SH_ACT + ac8;
    const __nv_bfloat16* bH = g_wsd_h + (size_t)bk * H_DIM + cb + bn8;
    const __nv_bfloat16* bL = g_wsd_l + (size_t)bk * H_DIM + cb + bn8;

    const uint32_t aBase = (uint32_t)((((wm * 16 + (lane & 15)) * SA) + (lane >> 4) * 8) * 2);
    uint32_t aOffH = (uint32_t)__cvta_generic_to_shared(sAh) + aBase;
    uint32_t aOffL = (uint32_t)__cvta_generic_to_shared(sAl) + aBase;
    const int mB = lane >> 3;
    const uint32_t bBase = (uint32_t)(((((mB & 1) * 8 + (lane & 7)) * SB) + wn * 32 + (mB >> 1) * 8) * 2);
    uint32_t bOffH = (uint32_t)__cvta_generic_to_shared(sBh) + bBase;
    uint32_t bOffL = (uint32_t)__cvta_generic_to_shared(sBl) + bBase;

    float acc[4][4] = {};

    for (int k0 = 0; k0 < SH_ACT; k0 += KC) {
        *(uint4*)&sAh[ar * SA + ac8] = *(const uint4*)(aH + k0);
        *(uint4*)&sAl[ar * SA + ac8] = *(const uint4*)(aL + k0);
        *(uint4*)&sBh[bk * SB + bn8] = *(const uint4*)(bH + (size_t)k0 * H_DIM);
        *(uint4*)&sBl[bk * SB + bn8] = *(const uint4*)(bL + (size_t)k0 * H_DIM);
        __syncthreads();
#pragma unroll
        for (int s = 0; s < 2; s++) {
            unsigned ah[4], al[4];
            ldsm4(ah, aOffH + s * 32);
            ldsm4(al, aOffL + s * 32);
            unsigned bh[8], bl[8];
#pragma unroll
            for (int g = 0; g < 2; g++) {
                uint32_t off = (uint32_t)(s * 16 * SB) * 2 + g * 32;
                ldsm4t(&bh[g * 4], bOffH + off);
                ldsm4t(&bl[g * 4], bOffL + off);
            }
#pragma unroll
            for (int t = 0; t < 4; t++) {
                int p = (t >> 1) * 4 + (t & 1) * 2;
                mma_bf16(acc[t], ah[0], ah[1], ah[2], ah[3], bh[p], bh[p + 1]);
                mma_bf16(acc[t], ah[0], ah[1], ah[2], ah[3], bl[p], bl[p + 1]);
                mma_bf16(acc[t], al[0], al[1], al[2], al[3], bh[p], bh[p + 1]);
            }
        }
        __syncthreads();
    }
    const int r0 = rb + wm * 16 + gid;
#pragma unroll
    for (int t = 0; t < 4; t++) {
        int c = cb + wn * 32 + t * 8 + tig * 2;
        out[(size_t)(r0    ) * H_DIM + c + 0] = acc[t][0];
        out[(size_t)(r0    ) * H_DIM + c + 1] = acc[t][1];
        out[(size_t)(r0 + 8) * H_DIM + c + 0] = acc[t][2];
        out[(size_t)(r0 + 8) * H_DIM + c + 1] = acc[t][3];
    }
}

// -------------------- routed gate_up (gathered rows) -----------------------
__global__ __launch_bounds__(256) void routed_gateup_tc()
{
    const int e = blockIdx.z;
    const int cnt = g_counts[e];
    const int r0b = blockIdx.y * 64;
    if (r0b >= cnt) return;

    __shared__ __align__(16) __nv_bfloat16 sAh[64 * SA], sAl[64 * SA];
    __shared__ __align__(16) __nv_bfloat16 sGh[KC * SB], sGl[KC * SB];
    __shared__ __align__(16) __nv_bfloat16 sUh[KC * SB], sUl[KC * SB];

    const int tid = threadIdx.x, lane = tid & 31, wid = tid >> 5;
    const int gid = lane >> 2, tig = lane & 3;
    const int wm = wid & 3, wn = wid >> 2;
    const int cb = blockIdx.x * 64;

    const int ar = tid >> 2, ac8 = (tid & 3) * 8;
    const int bk = tid >> 3, bn8 = (tid & 7) * 8;

    int tok = 0;
    {
        int r = r0b + ar;
        if (r < cnt) tok = g_list[e * CAP + r] / TOPK;
    }
    const __nv_bfloat16* aH = g_xs_h + (size_t)tok * H_DIM + ac8;
    const __nv_bfloat16* aL = g_xs_l + (size_t)tok * H_DIM + ac8;
    const __nv_bfloat16* gH = g_wgu_h + (size_t)e * H_DIM * GUP_COLS + (size_t)bk * GUP_COLS + cb + bn8;
    const __nv_bfloat16* gL = g_wgu_l + (size_t)e * H_DIM * GUP_COLS + (size_t)bk * GUP_COLS + cb + bn8;
    const __nv_bfloat16* uH = gH + I_DIM;
    const __nv_bfloat16* uL = gL + I_DIM;

    const uint32_t aBase = (uint32_t)((((wm * 16 + (lane & 15)) * SA) + (lane >> 4) * 8) * 2);
    uint32_t aOffH = (uint32_t)__cvta_generic_to_shared(sAh) + aBase;
    uint32_t aOffL = (uint32_t)__cvta_generic_to_shared(sAl) + aBase;
    const int mB = lane >> 3;
    const uint32_t bBase = (uint32_t)(((((mB & 1) * 8 + (lane & 7)) * SB) + wn * 32 + (mB >> 1) * 8) * 2);
    uint32_t gOffH = (uint32_t)__cvta_generic_to_shared(sGh) + bBase;
    uint32_t gOffL = (uint32_t)__cvta_generic_to_shared(sGl) + bBase;
    uint32_t uOffH = (uint32_t)__cvta_generic_to_shared(sUh) + bBase;
    uint32_t uOffL = (uint32_t)__cvta_generic_to_shared(sUl) + bBase;

    float accG[4][4] = {}, accU[4][4] = {};

    for (int k0 = 0; k0 < H_DIM; k0 += KC) {
        *(uint4*)&sAh[ar * SA + ac8] = *(const uint4*)(aH + k0);
        *(uint4*)&sAl[ar * SA + ac8] = *(const uint4*)(aL + k0);
        *(uint4*)&sGh[bk * SB + bn8] = *(const uint4*)(gH + (size_t)k0 * GUP_COLS);
        *(uint4*)&sGl[bk * SB + bn8] = *(const uint4*)(gL + (size_t)k0 * GUP_COLS);
        *(uint4*)&sUh[bk * SB + bn8] = *(const uint4*)(uH + (size_t)k0 * GUP_COLS);
        *(uint4*)&sUl[bk * SB + bn8] = *(const uint4*)(uL + (size_t)k0 * GUP_COLS);
        __syncthreads();
#pragma unroll
        for (int s = 0; s < 2; s++) {
            unsigned ah[4], al[4];
            ldsm4(ah, aOffH + s * 32);
            ldsm4(al, aOffL + s * 32);
            unsigned gh[8], gl[8], uh[8], ul[8];
#pragma unroll
            for (int g = 0; g < 2; g++) {
                uint32_t off = (uint32_t)(s * 16 * SB) * 2 + g * 32;
                ldsm4t(&gh[g * 4], gOffH + off);
                ldsm4t(&gl[g * 4], gOffL + off);
                ldsm4t(&uh[g * 4], uOffH + off);
                ldsm4t(&ul[g * 4], uOffL + off);
            }
#pragma unroll
            for (int t = 0; t < 4; t++) {
                int p = (t >> 1) * 4 + (t & 1) * 2;
                mma_bf16(accG[t], ah[0], ah[1], ah[2], ah[3], gh[p], gh[p + 1]);
                mma_bf16(accG[t], ah[0], ah[1], ah[2], ah[3], gl[p], gl[p + 1]);
                mma_bf16(accG[t], al[0], al[1], al[2], al[3], gh[p], gh[p + 1]);
                mma_bf16(accU[t], ah[0], ah[1], ah[2], ah[3], uh[p], uh[p + 1]);
                mma_bf16(accU[t], ah[0], ah[1], ah[2], ah[3], ul[p], ul[p + 1]);
                mma_bf16(accU[t], al[0], al[1], al[2], al[3], uh[p], uh[p + 1]);
            }
        }
        __syncthreads();
    }
    const int rw = wm * 16 + gid;
#pragma unroll
    for (int t = 0; t < 4; t++) {
        int c = cb + wn * 32 + t * 8 + tig * 2;
#pragma unroll
        for (int i = 0; i < 2; i++) {
            int r = r0b + rw + i * 8;
            if (r < cnt) {
                float g0 = accG[t][i * 2], u0 = accU[t][i * 2];
                float g1 = accG[t][i * 2 + 1], u1 = accU[t][i * 2 + 1];
                float a0 = (g0 / (1.f + expf(-g0))) * u0;
                float a1 = (g1 / (1.f + expf(-g1))) * u1;
                __nv_bfloat16 h0 = __float2bfloat16(a0), h1 = __float2bfloat16(a1);
                __nv_bfloat16 l0 = __float2bfloat16(a0 - __bfloat162float(h0));
                __nv_bfloat16 l1 = __float2bfloat16(a1 - __bfloat162float(h1));
                *(unsigned*)&g_actr_h[((size_t)e * CAP + r) * I_DIM + c] = pack2(h0, h1);
                *(unsigned*)&g_actr_l[((size_t)e * CAP + r) * I_DIM + c] = pack2(l0, l1);
            }
        }
    }
}

// ----------------------- routed down -> ybuf[a, H] -------------------------
__global__ __launch_bounds__(256) void routed_down_tc()
{
    const int e = blockIdx.z;
    const int cnt = g_counts[e];
    const int r0b = blockIdx.y * 64;
    if (r0b >= cnt) return;

    __shared__ __align__(16) __nv_bfloat16 sAh[64 * SA], sAl[64 * SA];
    __shared__ __align__(16) __nv_bfloat16 sBh[KC * SB], sBl[KC * SB];

    const int tid = threadIdx.x, lane = tid & 31, wid = tid >> 5;
    const int gid = lane >> 2, tig = lane & 3;
    const int wm = wid & 3, wn = wid >> 2;
    const int cb = blockIdx.x * 64;

    const int ar = tid >> 2, ac8 = (tid & 3) * 8;
    const int bk = tid >> 3, bn8 = (tid & 7) * 8;

    const __nv_bfloat16* aH = g_actr_h + ((size_t)e * CAP + (r0b + ar)) * I_DIM + ac8;
    const __nv_bfloat16* aL = g_actr_l + ((size_t)e * CAP + (r0b + ar)) * I_DIM + ac8;
    const __nv_bfloat16* bH = g_wd_h + (size_t)e * I_DIM * H_DIM + (size_t)bk * H_DIM + cb + bn8;
    const __nv_bfloat16* bL = g_wd_l + (size_t)e * I_DIM * H_DIM + (size_t)bk * H_DIM + cb + bn8;

    const uint32_t aBase = (uint32_t)((((wm * 16 + (lane & 15)) * SA) + (lane >> 4) * 8) * 2);
    uint32_t aOffH = (uint32_t)__cvta_generic_to_shared(sAh) + aBase;
    uint32_t aOffL = (uint32_t)__cvta_generic_to_shared(sAl) + aBase;
    const int mB = lane >> 3;
    const uint32_t bBase = (uint32_t)(((((mB & 1) * 8 + (lane & 7)) * SB) + wn * 32 + (mB >> 1) * 8) * 2);
    uint32_t bOffH = (uint32_t)__cvta_generic_to_shared(sBh) + bBase;
    uint32_t bOffL = (uint32_t)__cvta_generic_to_shared(sBl) + bBase;

    float acc[4][4] = {};

    for (int k0 = 0; k0 < I_DIM; k0 += KC) {
        *(uint4*)&sAh[ar * SA + ac8] = *(const uint4*)(aH + k0);
        *(uint4*)&sAl[ar * SA + ac8] = *(const uint4*)(aL + k0);
        *(uint4*)&sBh[bk * SB + bn8] = *(const uint4*)(bH + (size_t)k0 * H_DIM);
        *(uint4*)&sBl[bk * SB + bn8] = *(const uint4*)(bL + (size_t)k0 * H_DIM);
        __syncthreads();
#pragma unroll
        for (int s = 0; s < 2; s++) {
            unsigned ah[4], al[4];
            ldsm4(ah, aOffH + s * 32);
            ldsm4(al, aOffL + s * 32);
            unsigned bh[8], bl[8];
#pragma unroll
            for (int g = 0; g < 2; g++) {
                uint32_t off = (uint32_t)(s * 16 * SB) * 2 + g * 32;
                ldsm4t(&bh[g * 4], bOffH + off);
                ldsm4t(&bl[g * 4], bOffL + off);
            }
#pragma unroll
            for (int t = 0; t < 4; t++) {
                int p = (t >> 1) * 4 + (t & 1) * 2;
                mma_bf16(acc[t], ah[0], ah[1], ah[2], ah[3], bh[p], bh[p + 1]);
                mma_bf16(acc[t], ah[0], ah[1], ah[2], ah[3], bl[p], bl[p + 1]);
                mma_bf16(acc[t], al[0], al[1], al[2], al[3], bh[p], bh[p + 1]);
            }
        }
        __syncthreads();
    }
    const int rw = wm * 16 + gid;
#pragma unroll
    for (int t = 0; t < 4; t++) {
        int c = cb + wn * 32 + t * 8 + tig * 2;
#pragma unroll
        for (int i = 0; i < 2; i++) {
            int r = r0b + rw + i * 8;
            if (r < cnt) {
                int a = g_list[e * CAP + r];
                g_ybuf[(size_t)a * H_DIM + c + 0] = acc[t][i * 2 + 0];
                g_ybuf[(size_t)a * H_DIM + c + 1] = acc[t][i * 2 + 1];
            }
        }
    }
}

// ------------------------------- combine -----------------------------------
__global__ __launch_bounds__(256) void combine_kernel(float* __restrict__ out)
{
    const int t = blockIdx.x;
    const int h4 = threadIdx.x * 4;
    float4 o = *(float4*)(out + (size_t)t * H_DIM + h4);
    float r0 = o.x, r1 = o.y, r2 = o.z, r3 = o.w;
#pragma unroll
    for (int k = 0; k < TOPK; k++) {
        int a = t * TOPK + k;
        if (g_keep[a]) {
            float wv = g_w[a] * SCALE_F;
            float4 y = *(const float4*)(g_ybuf + (size_t)a * H_DIM + h4);
            r0 += wv * y.x; r1 += wv * y.y; r2 += wv * y.z; r3 += wv * y.w;
        }
    }
    *(float4*)(out + (size_t)t * H_DIM + h4) = make_float4(r0, r1, r2, r3);
}

// ------------------------------- launcher ----------------------------------
extern "C" void kernel_launch(void* const* d_in, const int* in_sizes, int n_in,
                              void* d_out, int out_size)
{
    const float* x          = (const float*)d_in[0];
    const float* gate_w     = (const float*)d_in[1];
    const float* e_bias     = (const float*)d_in[2];
    const float* w_gate_up  = (const float*)d_in[3];
    const float* w_down     = (const float*)d_in[4];
    const float* ws_gate_up = (const float*)d_in[5];
    const float* ws_down    = (const float*)d_in[6];
    float* out = (float*)d_out;

    __nv_bfloat16 *xs_h, *xs_l, *wsgu_h, *wsgu_l, *wsd_h, *wsd_l;
    __nv_bfloat16 *wgu_h, *wgu_l, *wd_h, *wd_l;
    cudaGetSymbolAddress((void**)&xs_h, g_xs_h);
    cudaGetSymbolAddress((void**)&xs_l, g_xs_l);
    cudaGetSymbolAddress((void**)&wsgu_h, g_wsgu_h);
    cudaGetSymbolAddress((void**)&wsgu_l, g_wsgu_l);
    cudaGetSymbolAddress((void**)&wsd_h, g_wsd_h);
    cudaGetSymbolAddress((void**)&wsd_l, g_wsd_l);
    cudaGetSymbolAddress((void**)&wgu_h, g_wgu_h);
    cudaGetSymbolAddress((void**)&wgu_l, g_wgu_l);
    cudaGetSymbolAddress((void**)&wd_h, g_wd_h);
    cudaGetSymbolAddress((void**)&wd_l, g_wd_l);

    auto split = [](const float* s, __nv_bfloat16* h, __nv_bfloat16* l, size_t n) {
        int n4 = (int)(n / 4);
        split_kernel<<<(n4 + 255) / 256, 256>>>((const float4*)s, (uint2*)h, (uint2*)l, n4);
    };

    split(x,          xs_h,   xs_l,   (size_t)T_TOK * H_DIM);
    split(ws_gate_up, wsgu_h, wsgu_l, (size_t)H_DIM * SH_GUP);
    split(ws_down,    wsd_h,  wsd_l,  (size_t)SH_ACT * H_DIM);
    split(w_gate_up,  wgu_h,  wgu_l,  (size_t)E_EXP * H_DIM * GUP_COLS);
    split(w_down,     wd_h,   wd_l,   (size_t)E_EXP * I_DIM * H_DIM);

    router_kernel<<<T_TOK, 256>>>(x, gate_w, e_bias);
    dispatch_kernel<<<E_EXP, 256>>>();

    shared_gateup_tc<<<dim3(SH_ACT / 64, T_TOK / 64), 256>>>();
    shared_down_tc<<<dim3(H_DIM / 64, T_TOK / 64), 256>>>(out);
    routed_gateup_tc<<<dim3(I_DIM / 64, CAP / 64, E_EXP), 256>>>();
    routed_down_tc<<<dim3(H_DIM / 64, CAP / 64, E_EXP), 256>>>();
    combine_kernel<<<T_TOK, 256>>>(out);
}